// round 4
// baseline (speedup 1.0000x reference)
#include <cuda_runtime.h>

#define T_STEPS 168
#define IN_DIM  16
#define NH1     64
#define NH2     32
#define NG1     256
#define NG2     128
#define BATCH   4096

#define NB   28
#define BLK  384          // 256 layer-1 threads + 128 layer-2 threads
#define GRID ((BATCH + NB - 1) / NB)   // 147

#define IN1_STRIDE 84     // 16 x + 64 h1 + 4 pad (16B-aligned rows)

// shared layout (floats)
#define OFF_H1B 0                              // h1 double buffer [2][28][64]
#define OFF_IN1 (OFF_H1B + 2 * NB * NH1)       // [28][84]  x | h1 state
#define OFF_H2  (OFF_IN1 + NB * IN1_STRIDE)    // [28][32]  h2 state
#define OFF_G1  (OFF_H2  + NB * NH2)           // [28][256] layer-1 gates
#define OFF_G2  (OFF_G1  + NB * NG1)           // [28][128] layer-2 gates
#define SMEM_FLOATS (OFF_G2 + NB * NG2)        // 17584 floats = 70336 B

typedef unsigned long long u64;

__device__ __forceinline__ void fma2(u64& d, u64 a, u64 b) {
    asm("fma.rn.f32x2 %0, %1, %2, %0;" : "+l"(d) : "l"(a), "l"(b));
}
__device__ __forceinline__ u64 pack2(float lo, float hi) {
    u64 r; asm("mov.b64 %0, {%1, %2};" : "=l"(r) : "f"(lo), "f"(hi)); return r;
}
__device__ __forceinline__ float pairsum(u64 v) {
    float lo, hi;
    asm("mov.b64 {%0, %1}, %2;" : "=f"(lo), "=f"(hi) : "l"(v));
    return lo + hi;
}
__device__ __forceinline__ float sigm_(float v) {
    v = fminf(fmaxf(v, -30.f), 30.f);
    return __fdividef(1.f, 1.f + __expf(-v));
}
__device__ __forceinline__ float tanh_(float v) {
    v = fminf(fmaxf(v, -15.f), 15.f);
    float e = __expf(2.f * v);
    return __fdividef(e - 1.f, e + 1.f);
}

extern __shared__ float smem[];

__global__ __launch_bounds__(BLK, 1)
void lstm2_ws_kernel(const float* __restrict__ x,
                     const float* __restrict__ Wih1, const float* __restrict__ Whh1,
                     const float* __restrict__ bih1, const float* __restrict__ bhh1,
                     const float* __restrict__ Wih2, const float* __restrict__ Whh2,
                     const float* __restrict__ bih2, const float* __restrict__ bhh2,
                     const float* __restrict__ Wfc,  const float* __restrict__ bfc,
                     float* __restrict__ out)
{
    const int tid = threadIdx.x;
    const int b0  = blockIdx.x * NB;

    float* h1buf = smem + OFF_H1B;
    float* sIn1  = smem + OFF_IN1;
    float* sH2   = smem + OFF_H2;
    float* sG1   = smem + OFF_G1;
    float* sG2   = smem + OFF_G2;

    // zero the recurrent state (h1buf, sIn1, sH2)
    for (int i = tid; i < OFF_G1; i += BLK) smem[i] = 0.f;

    const bool isL1 = (tid < 256);

    if (isL1) {
        // ================= LAYER-1 THREAD (one gate row, 28 batches) =================
        const int g = tid;
        u64 w1r[40];
        {
            const float4* wi = (const float4*)(Wih1 + g * IN_DIM);
#pragma unroll
            for (int i = 0; i < 4; i++) {
                float4 v = wi[i];
                w1r[2 * i]     = pack2(v.x, v.y);
                w1r[2 * i + 1] = pack2(v.z, v.w);
            }
            const float4* wh = (const float4*)(Whh1 + g * NH1);
#pragma unroll
            for (int i = 0; i < 16; i++) {
                float4 v = wh[i];
                w1r[8 + 2 * i] = pack2(v.x, v.y);
                w1r[9 + 2 * i] = pack2(v.z, v.w);
            }
        }
        const float bias1 = bih1[g] + bhh1[g];
        const bool  gtanh = (g >= 128) && (g < 192);

        float c1[7];
#pragma unroll
        for (int j = 0; j < 7; j++) c1[j] = 0.f;

        // x publishers: 112 threads, one float4 each
        const bool xact = (tid < NB * 4);
        const int  xb = tid >> 2, xk4 = tid & 3;
        const bool xval = xact && (b0 + xb) < BATCH;
        const float* xptr = x + ((long)(b0 + xb) * T_STEPS) * IN_DIM + xk4 * 4;
        float4 xreg = make_float4(0.f, 0.f, 0.f, 0.f);
        if (xval) xreg = *(const float4*)xptr;

        __syncthreads();                                   // P1
        if (xact) *(float4*)&sIn1[xb * IN1_STRIDE + xk4 * 4] = xreg;   // x(0)
        if (xval) xreg = *(const float4*)(xptr + IN_DIM);              // x(1)
        __syncthreads();                                   // P2

        for (int t = 0; t <= T_STEPS; t++) {
            if (t < T_STEPS) {
                // ---- gates: two halves of 14 batches ----
#pragma unroll 1
                for (int half = 0; half < 2; half++) {
                    const float* in1 = sIn1 + (half * 14) * IN1_STRIDE;
                    u64 acc[14];
#pragma unroll
                    for (int b = 0; b < 14; b++) acc[b] = pack2(bias1, 0.f);
#pragma unroll
                    for (int k4 = 0; k4 < 20; k4++) {
#pragma unroll
                        for (int b = 0; b < 14; b++) {
                            const ulonglong2 h =
                                *(const ulonglong2*)(in1 + b * IN1_STRIDE + k4 * 4);
                            fma2(acc[b], w1r[2 * k4],     h.x);
                            fma2(acc[b], w1r[2 * k4 + 1], h.y);
                        }
                    }
#pragma unroll
                    for (int b = 0; b < 14; b++) {
                        const float v = pairsum(acc[b]);
                        sG1[(half * 14 + b) * NG1 + g] = gtanh ? tanh_(v) : sigm_(v);
                    }
                }
                asm volatile("bar.sync 1, 256;" ::: "memory");

                // publish x(t+1), prefetch x(t+2)
                if (xact && (t + 1) < T_STEPS)
                    *(float4*)&sIn1[xb * IN1_STRIDE + xk4 * 4] = xreg;
                if (xval && (t + 2) < T_STEPS)
                    xreg = *(const float4*)(xptr + (long)(t + 2) * IN_DIM);

                // ---- cell/h update: 7 fixed units per thread ----
                float* h1o = h1buf + (t & 1) * (NB * NH1);
#pragma unroll
                for (int j = 0; j < 7; j++) {
                    const int id = tid + 256 * j;
                    const int b = id >> 6, u = id & 63;
                    const float i_ = sG1[b * NG1 + u];
                    const float f_ = sG1[b * NG1 + NH1 + u];
                    const float g_ = sG1[b * NG1 + 2 * NH1 + u];
                    const float o_ = sG1[b * NG1 + 3 * NH1 + u];
                    const float c = fmaf(f_, c1[j], i_ * g_);
                    c1[j] = c;
                    const float h = o_ * tanh_(c);
                    sIn1[b * IN1_STRIDE + IN_DIM + u] = h;
                    h1o[b * NH1 + u] = h;
                }
            }
            __syncthreads();                               // per-step global sync
        }
    } else {
        // ================= LAYER-2 THREAD (one gate row, 28 batches) =================
        const int g = tid - 256;   // 0..127
        u64 w2r[48];
        {
            const float4* wi = (const float4*)(Wih2 + g * NH1);
#pragma unroll
            for (int i = 0; i < 16; i++) {
                float4 v = wi[i];
                w2r[2 * i]     = pack2(v.x, v.y);
                w2r[2 * i + 1] = pack2(v.z, v.w);
            }
            const float4* wh = (const float4*)(Whh2 + g * NH2);
#pragma unroll
            for (int i = 0; i < 8; i++) {
                float4 v = wh[i];
                w2r[32 + 2 * i] = pack2(v.x, v.y);
                w2r[33 + 2 * i] = pack2(v.z, v.w);
            }
        }
        const float bias2 = bih2[g] + bhh2[g];
        const bool  gtanh = (g >= 64) && (g < 96);

        float c2[7];
#pragma unroll
        for (int j = 0; j < 7; j++) c2[j] = 0.f;

        __syncthreads();                                   // P1
        __syncthreads();                                   // P2

        for (int t = 0; t <= T_STEPS; t++) {
            if (t >= 1) {
                // layer-2 computes step (t-1): h1 from buffer (t-1)&1
                const float* h1p = h1buf + ((t - 1) & 1) * (NB * NH1);
#pragma unroll 1
                for (int half = 0; half < 2; half++) {
                    const float* h1q = h1p + (half * 14) * NH1;
                    const float* h2q = sH2 + (half * 14) * NH2;
                    u64 acc[14];
#pragma unroll
                    for (int b = 0; b < 14; b++) acc[b] = pack2(bias2, 0.f);
#pragma unroll
                    for (int k4 = 0; k4 < 16; k4++) {
#pragma unroll
                        for (int b = 0; b < 14; b++) {
                            const ulonglong2 h =
                                *(const ulonglong2*)(h1q + b * NH1 + k4 * 4);
                            fma2(acc[b], w2r[2 * k4],     h.x);
                            fma2(acc[b], w2r[2 * k4 + 1], h.y);
                        }
                    }
#pragma unroll
                    for (int k4 = 0; k4 < 8; k4++) {
#pragma unroll
                        for (int b = 0; b < 14; b++) {
                            const ulonglong2 h =
                                *(const ulonglong2*)(h2q + b * NH2 + k4 * 4);
                            fma2(acc[b], w2r[32 + 2 * k4], h.x);
                            fma2(acc[b], w2r[33 + 2 * k4], h.y);
                        }
                    }
#pragma unroll
                    for (int b = 0; b < 14; b++) {
                        const float v = pairsum(acc[b]);
                        sG2[(half * 14 + b) * NG2 + g] = gtanh ? tanh_(v) : sigm_(v);
                    }
                }
                asm volatile("bar.sync 2, 128;" ::: "memory");

                // cell/h update: 7 fixed units per thread
#pragma unroll
                for (int j = 0; j < 7; j++) {
                    const int id = (tid - 256) + 128 * j;
                    const int b = id >> 5, u = id & 31;
                    const float i_ = sG2[b * NG2 + u];
                    const float f_ = sG2[b * NG2 + NH2 + u];
                    const float g_ = sG2[b * NG2 + 2 * NH2 + u];
                    const float o_ = sG2[b * NG2 + 3 * NH2 + u];
                    const float c = fmaf(f_, c2[j], i_ * g_);
                    c2[j] = c;
                    sH2[b * NH2 + u] = o_ * tanh_(c);
                }
            }
            __syncthreads();                               // per-step global sync
        }
    }

    // ---- final FC: out[b] = h2(T-1) . Wfc + bfc ----
    if (tid < NB) {
        const int bg = b0 + tid;
        if (bg < BATCH) {
            float s = bfc[0];
#pragma unroll
            for (int u = 0; u < NH2; u++)
                s = fmaf(sH2[tid * NH2 + u], Wfc[u], s);
            out[bg] = s;
        }
    }
}

extern "C" void kernel_launch(void* const* d_in, const int* in_sizes, int n_in,
                              void* d_out, int out_size)
{
    const float* x    = (const float*)d_in[0];
    const float* Wih1 = (const float*)d_in[1];
    const float* Whh1 = (const float*)d_in[2];
    const float* bih1 = (const float*)d_in[3];
    const float* bhh1 = (const float*)d_in[4];
    const float* Wih2 = (const float*)d_in[5];
    const float* Whh2 = (const float*)d_in[6];
    const float* bih2 = (const float*)d_in[7];
    const float* bhh2 = (const float*)d_in[8];
    const float* Wfc  = (const float*)d_in[9];
    const float* bfc  = (const float*)d_in[10];
    float* out = (float*)d_out;

    const size_t smem_bytes = SMEM_FLOATS * sizeof(float);  // ~70 KB
    cudaFuncSetAttribute(lstm2_ws_kernel,
                         cudaFuncAttributeMaxDynamicSharedMemorySize,
                         (int)smem_bytes);

    lstm2_ws_kernel<<<GRID, BLK, smem_bytes>>>(
        x, Wih1, Whh1, bih1, bhh1, Wih2, Whh2, bih2, bhh2, Wfc, bfc, out);
}